// round 14
// baseline (speedup 1.0000x reference)
#include <cuda_runtime.h>
#include <cuda_bf16.h>

// CBOW negative-sampling loss — single fused kernel with cross-task
// L2 software prefetch.
// Inputs (metadata order):
//   d_in[0] i_emb        float32  (VOCAB+1, 50)
//   d_in[1] o_emb        float32  (VOCAB+1, 50)
//   d_in[2] target_wids  int32    (B,)
//   d_in[3] context_wids int32    (B, 10)
//   d_in[4] neg_wids     int32    (B, 10)
// Output: scalar float32 = -( sum log_sigmoid(pos) + sum log_sigmoid(-neg) )
//
// Theory: all prior variants pin at ~2.7 TB/s because the per-SM
// outstanding-line pool (~64 L1tex lines, shared with cp.async) is
// saturated; throughput = pool / line-hold-time. An L2 hit releases a line
// ~3x faster than a DRAM miss. Each warp therefore processes 4 rows and
// prefetches (prefetch.global.L2) all 21 embedding rows of task t+1 before
// computing task t: compute time (~1-2us) >> DRAM latency (~400ns), so
// 75% of dependent gathers become L2 hits. Per-lane prefetch: lane s owns
// row s; 2 lines always, 3rd predicated on (off&127)>56 -> no extra bytes.

#define DIM2  25     // 50 floats = 25 float2
#define CTX   10
#define NNEG  10
#define TPW   4      // tasks (batch rows) per warp
#define ROWB  200u
#define MAX_BLOCKS 8192

__device__ float        g_partials[MAX_BLOCKS];
__device__ unsigned int g_count = 0;   // module-load init; reset by last block

__device__ __forceinline__ float log_sigmoid(float x) {
    // min(x,0) - log(1 + exp(-|x|)); log arg in (1,2] -> __logf is safe
    return fminf(x, 0.0f) - __logf(1.0f + __expf(-fabsf(x)));
}

__device__ __forceinline__ void pf_l2(const char* p) {
    asm volatile("prefetch.global.L2 [%0];" :: "l"(p));
}

// Prefetch all 21 embedding rows of batch row `task` (lane s owns row s).
__device__ __forceinline__ void prefetch_task(
    const char* ib, const char* ob,
    const int* target_wids, const int* context_wids, const int* neg_wids,
    int task, int lane)
{
    if (lane < 21) {
        int idx;
        const char* tab;
        if (lane < CTX)      { idx = __ldg(&context_wids[task * CTX + lane]); tab = ib; }
        else if (lane == CTX){ idx = __ldg(&target_wids[task]);               tab = ob; }
        else                 { idx = __ldg(&neg_wids[task * NNEG + lane - CTX - 1]); tab = ob; }
        const unsigned off  = (unsigned)idx * ROWB;
        const char*    base = tab + (off & ~127u);
        pf_l2(base);
        pf_l2(base + 128);
        if ((off & 127u) > 56u) pf_l2(base + 256);   // row spans a 3rd line
    }
}

// Reduce two independent per-lane partials A,B across the warp in 5 shfls.
// Post: lane 0 holds full sum of A; lane 16 holds full sum of B.
__device__ __forceinline__ float pair_reduce(float A, float B, int lane) {
    float x = (lane & 16) ? A : B;
    float y = __shfl_xor_sync(0xFFFFFFFFu, x, 16);
    float v = ((lane & 16) ? B : A) + y;
    v += __shfl_xor_sync(0xFFFFFFFFu, v, 8);
    v += __shfl_xor_sync(0xFFFFFFFFu, v, 4);
    v += __shfl_xor_sync(0xFFFFFFFFu, v, 2);
    v += __shfl_xor_sync(0xFFFFFFFFu, v, 1);
    return v;
}

__global__ void __launch_bounds__(128) cbow_pf_kernel(
    const float* __restrict__ i_emb,
    const float* __restrict__ o_emb,
    const int*   __restrict__ target_wids,
    const int*   __restrict__ context_wids,
    const int*   __restrict__ neg_wids,
    float*       __restrict__ out,
    int B)
{
    const int warp_global = (blockIdx.x * blockDim.x + threadIdx.x) >> 5;
    const int lane        = threadIdx.x & 31;
    const int warp_local  = threadIdx.x >> 5;

    __shared__ float  s_partial[4];
    __shared__ int    s_is_last;
    __shared__ double s_d[4];

    const char* ib = (const char*)i_emb;
    const char* ob = (const char*)o_emb;
    const float2* __restrict__ i2 = (const float2*)i_emb;
    const float2* __restrict__ o2 = (const float2*)o_emb;
    const float inv_ctx = 1.0f / CTX;

    float loss = 0.0f;   // meaningful only on lanes 0 and 16 until combined

    const int t0 = warp_global * TPW;

    // warm the pipe: prefetch the first task's rows (no distance, but merges)
    if (t0 < B)
        prefetch_task(ib, ob, target_wids, context_wids, neg_wids, t0, lane);

    #pragma unroll
    for (int t = 0; t < TPW; t++) {
        const int task = t0 + t;
        if (task >= B) break;

        // prefetch next task's 21 rows before computing this one
        if (t + 1 < TPW && task + 1 < B)
            prefetch_task(ib, ob, target_wids, context_wids, neg_wids,
                          task + 1, lane);

        const int* __restrict__ cw = context_wids + task * CTX;
        const int* __restrict__ nw = neg_wids     + task * NNEG;

        // ---- 32-bit row offsets (max 200001*25 = 5000025 < 2^31) ----
        int cb[CTX], nb[NNEG], tb;
        #pragma unroll
        for (int c = 0; c < CTX; c++)  cb[c] = __ldg(&cw[c]) * DIM2;
        tb = __ldg(&target_wids[task]) * DIM2;
        #pragma unroll
        for (int n = 0; n < NNEG; n++) nb[n] = __ldg(&nw[n]) * DIM2;

        float ax = 0.0f, ay = 0.0f;
        float p[NNEG + 1];
        #pragma unroll
        for (int k = 0; k <= NNEG; k++) p[k] = 0.0f;

        if (lane < DIM2) {
            // ---- sum of context embeddings ----
            #pragma unroll
            for (int c = 0; c < CTX; c++) {
                const float2 e = __ldg(&i2[cb[c] + lane]);
                ax += e.x;  ay += e.y;
            }
            // ---- 11 per-lane score partials ----
            {
                const float2 e = __ldg(&o2[tb + lane]);
                p[0] = e.x * ax + e.y * ay;
            }
            #pragma unroll
            for (int n = 0; n < NNEG; n++) {
                const float2 e = __ldg(&o2[nb[n] + lane]);
                p[n + 1] = e.x * ax + e.y * ay;
            }
        }

        // pair 0: (pos, neg0) — mixed signs
        {
            float v = pair_reduce(p[0], p[1], lane);
            if ((lane & 15) == 0) {
                float sc = v * inv_ctx;
                loss += log_sigmoid((lane & 16) ? -sc : sc);
            }
        }
        // pairs (neg1,neg2) (neg3,neg4) (neg5,neg6) (neg7,neg8)
        #pragma unroll
        for (int k = 2; k <= 8; k += 2) {
            float v = pair_reduce(p[k], p[k + 1], lane);
            if ((lane & 15) == 0)
                loss += log_sigmoid(-v * inv_ctx);
        }
        // leftover neg9: plain butterfly, accumulate at lane 0 only
        {
            float v = p[10];
            #pragma unroll
            for (int o = 16; o > 0; o >>= 1)
                v += __shfl_xor_sync(0xFFFFFFFFu, v, o);
            if (lane == 0)
                loss += log_sigmoid(-v * inv_ctx);
        }
    }

    // combine lanes 0 and 16
    loss += __shfl_xor_sync(0xFFFFFFFFu, loss, 16);
    if (lane == 0) s_partial[warp_local] = loss;
    __syncthreads();

    // block partial + last-block ticket
    if (threadIdx.x == 0) {
        float blk = s_partial[0] + s_partial[1] + s_partial[2] + s_partial[3];
        g_partials[blockIdx.x] = blk;
        __threadfence();
        unsigned int old = atomicAdd(&g_count, 1u);
        s_is_last = (old == gridDim.x - 1);
    }
    __syncthreads();

    if (s_is_last) {
        const int nb2 = gridDim.x;
        volatile float* vp = g_partials;   // writers fenced before the ticket
        double acc = 0.0;
        for (int i = threadIdx.x; i < nb2; i += 128)
            acc += (double)vp[i];
        #pragma unroll
        for (int o = 16; o > 0; o >>= 1)
            acc += __shfl_xor_sync(0xFFFFFFFFu, acc, o);
        if ((threadIdx.x & 31) == 0) s_d[threadIdx.x >> 5] = acc;
        __syncthreads();
        if (threadIdx.x == 0) {
            out[0] = (float)(-(s_d[0] + s_d[1] + s_d[2] + s_d[3]));
            g_count = 0;   // reset for next graph replay
        }
    }
}

extern "C" void kernel_launch(void* const* d_in, const int* in_sizes, int n_in,
                              void* d_out, int out_size)
{
    const float* i_emb        = (const float*)d_in[0];
    const float* o_emb        = (const float*)d_in[1];
    const int*   target_wids  = (const int*)d_in[2];
    const int*   context_wids = (const int*)d_in[3];
    const int*   neg_wids     = (const int*)d_in[4];
    float*       out          = (float*)d_out;

    const int B = in_sizes[2];
    const int rows_per_block = 4 * TPW;     // 4 warps x 4 tasks
    int blocks = (B + rows_per_block - 1) / rows_per_block;
    if (blocks > MAX_BLOCKS) blocks = MAX_BLOCKS;   // B=16384 -> 1024 blocks

    cbow_pf_kernel<<<blocks, 128>>>(i_emb, o_emb, target_wids,
                                    context_wids, neg_wids, out, B);
}

// round 15
// speedup vs baseline: 1.1194x; 1.1194x over previous
#include <cuda_runtime.h>
#include <cuda_bf16.h>

// CBOW negative-sampling loss — single fused kernel.
// Inputs (metadata order):
//   d_in[0] i_emb        float32  (VOCAB+1, 50)
//   d_in[1] o_emb        float32  (VOCAB+1, 50)
//   d_in[2] target_wids  int32    (B,)
//   d_in[3] context_wids int32    (B, 10)
//   d_in[4] neg_wids     int32    (B, 10)
// Output: scalar float32 = -( sum log_sigmoid(pos) + sum log_sigmoid(-neg) )
//
// One warp per row, 128-thread blocks. Lanes 0..24 load one float2 per row
// gather (rows are 200 B, 8B-aligned). 32-bit index math. Pairwise score
// reduction (5 shfls / 2 scores). Single launch via last-block ticket.
//
// R14 change (one variable vs the 18.43us best): i_emb gathers use
// ld.global.cs (evict-first). Measured cross-replay L2 hit rate is ~0
// (48 MB DRAM/launch = unique-row bytes) because the two 40 MB tables evict
// each other in an effectively ~50 MB L2. Demoting the i_emb stream in
// replacement (no carve-out needed, unlike evict_last) lets the o_emb table
// stay resident across graph replays -> target ~26 MB DRAM/launch.

#define DIM2 25    // 50 floats = 25 float2
#define CTX  10
#define NNEG 10
#define MAX_BLOCKS 8192

__device__ float        g_partials[MAX_BLOCKS];
__device__ unsigned int g_count = 0;   // module-load init; reset by last block

__device__ __forceinline__ float log_sigmoid(float x) {
    // min(x,0) - log(1 + exp(-|x|)); log arg in (1,2] -> __logf is safe
    return fminf(x, 0.0f) - __logf(1.0f + __expf(-fabsf(x)));
}

// i_emb load: evict-first / streaming hint (honored without L2 carve-out).
__device__ __forceinline__ float2 ldg_stream(const float2* p) {
    float2 r;
    asm("ld.global.cs.v2.f32 {%0,%1}, [%2];"
        : "=f"(r.x), "=f"(r.y) : "l"(p));
    return r;
}

// Reduce two independent per-lane partials A,B across the warp in 5 shfls.
// Post: lane 0 holds full sum of A; lane 16 holds full sum of B.
__device__ __forceinline__ float pair_reduce(float A, float B, int lane) {
    float x = (lane & 16) ? A : B;
    float y = __shfl_xor_sync(0xFFFFFFFFu, x, 16);
    float v = ((lane & 16) ? B : A) + y;
    v += __shfl_xor_sync(0xFFFFFFFFu, v, 8);
    v += __shfl_xor_sync(0xFFFFFFFFu, v, 4);
    v += __shfl_xor_sync(0xFFFFFFFFu, v, 2);
    v += __shfl_xor_sync(0xFFFFFFFFu, v, 1);
    return v;
}

__global__ void __launch_bounds__(128) cbow_fused_kernel(
    const float* __restrict__ i_emb,
    const float* __restrict__ o_emb,
    const int*   __restrict__ target_wids,
    const int*   __restrict__ context_wids,
    const int*   __restrict__ neg_wids,
    float*       __restrict__ out,
    int B)
{
    const int warp_global = (blockIdx.x * blockDim.x + threadIdx.x) >> 5;
    const int lane        = threadIdx.x & 31;
    const int warp_local  = threadIdx.x >> 5;

    __shared__ float  s_partial[4];
    __shared__ int    s_is_last;
    __shared__ double s_d[4];

    float loss = 0.0f;   // meaningful only on lanes 0 and 16 until combined

    if (warp_global < B) {
        const float2* __restrict__ i2 = (const float2*)i_emb;
        const float2* __restrict__ o2 = (const float2*)o_emb;
        const int*    __restrict__ cw = context_wids + warp_global * CTX;
        const int*    __restrict__ nw = neg_wids     + warp_global * NNEG;

        // ---- 32-bit row offsets (max 200001*25 = 5000025 < 2^31) ----
        int cb[CTX], nb[NNEG], tb;
        #pragma unroll
        for (int c = 0; c < CTX; c++)  cb[c] = __ldg(&cw[c]) * DIM2;
        tb = __ldg(&target_wids[warp_global]) * DIM2;
        #pragma unroll
        for (int n = 0; n < NNEG; n++) nb[n] = __ldg(&nw[n]) * DIM2;

        float ax = 0.0f, ay = 0.0f;
        float p[NNEG + 1];
        #pragma unroll
        for (int k = 0; k <= NNEG; k++) p[k] = 0.0f;

        if (lane < DIM2) {
            // ---- sum of context embeddings (i_emb: evict-first stream) ----
            #pragma unroll
            for (int c = 0; c < CTX; c++) {
                const float2 e = ldg_stream(&i2[cb[c] + lane]);
                ax += e.x;  ay += e.y;
            }
            // ---- 11 per-lane score partials (o_emb: default policy) ----
            {
                const float2 e = __ldg(&o2[tb + lane]);
                p[0] = e.x * ax + e.y * ay;
            }
            #pragma unroll
            for (int n = 0; n < NNEG; n++) {
                const float2 e = __ldg(&o2[nb[n] + lane]);
                p[n + 1] = e.x * ax + e.y * ay;
            }
        }

        const float inv_ctx = 1.0f / CTX;

        // pair 0: (pos, neg0) — mixed signs
        {
            float v = pair_reduce(p[0], p[1], lane);
            if ((lane & 15) == 0) {
                float sc = v * inv_ctx;
                loss += log_sigmoid((lane & 16) ? -sc : sc);
            }
        }
        // pairs (neg1,neg2) (neg3,neg4) (neg5,neg6) (neg7,neg8)
        #pragma unroll
        for (int k = 2; k <= 8; k += 2) {
            float v = pair_reduce(p[k], p[k + 1], lane);
            if ((lane & 15) == 0)
                loss += log_sigmoid(-v * inv_ctx);
        }
        // leftover neg9: plain butterfly, accumulate at lane 0 only
        {
            float v = p[10];
            #pragma unroll
            for (int o = 16; o > 0; o >>= 1)
                v += __shfl_xor_sync(0xFFFFFFFFu, v, o);
            if (lane == 0)
                loss += log_sigmoid(-v * inv_ctx);
        }
    }

    // combine lanes 0 and 16
    loss += __shfl_xor_sync(0xFFFFFFFFu, loss, 16);
    if (lane == 0) s_partial[warp_local] = loss;
    __syncthreads();

    // block partial + last-block ticket
    if (threadIdx.x == 0) {
        float blk = s_partial[0] + s_partial[1] + s_partial[2] + s_partial[3];
        g_partials[blockIdx.x] = blk;
        __threadfence();
        unsigned int old = atomicAdd(&g_count, 1u);
        s_is_last = (old == gridDim.x - 1);
    }
    __syncthreads();

    if (s_is_last) {
        const int nb2 = gridDim.x;
        volatile float* vp = g_partials;   // writers fenced before the ticket
        double acc = 0.0;
        for (int i = threadIdx.x; i < nb2; i += 128)
            acc += (double)vp[i];
        #pragma unroll
        for (int o = 16; o > 0; o >>= 1)
            acc += __shfl_xor_sync(0xFFFFFFFFu, acc, o);
        if ((threadIdx.x & 31) == 0) s_d[threadIdx.x >> 5] = acc;
        __syncthreads();
        if (threadIdx.x == 0) {
            out[0] = (float)(-(s_d[0] + s_d[1] + s_d[2] + s_d[3]));
            g_count = 0;   // reset for next graph replay
        }
    }
}

extern "C" void kernel_launch(void* const* d_in, const int* in_sizes, int n_in,
                              void* d_out, int out_size)
{
    const float* i_emb        = (const float*)d_in[0];
    const float* o_emb        = (const float*)d_in[1];
    const int*   target_wids  = (const int*)d_in[2];
    const int*   context_wids = (const int*)d_in[3];
    const int*   neg_wids     = (const int*)d_in[4];
    float*       out          = (float*)d_out;

    const int B = in_sizes[2];
    const int warps_per_block = 128 / 32;   // 4
    int blocks = (B + warps_per_block - 1) / warps_per_block;
    if (blocks > MAX_BLOCKS) blocks = MAX_BLOCKS;   // B=16384 -> 4096 blocks

    cbow_fused_kernel<<<blocks, 128>>>(i_emb, o_emb, target_wids,
                                       context_wids, neg_wids, out, B);
}

// round 16
// speedup vs baseline: 1.1311x; 1.0105x over previous
#include <cuda_runtime.h>
#include <cuda_bf16.h>

// CBOW negative-sampling loss — dual-path gather kernel.
//   i_emb (10 ctx rows/task)  -> LDG path (L1tex miss pool, ~55 lines/SM)
//   o_emb (11 rows/task)      -> cp.async.bulk path (TMA queue) into SMEM
// The two outstanding-request pools are independent, so bytes-in-flight add.
//
// Inputs (metadata order):
//   d_in[0] i_emb  f32 (VOCAB+1,50) | d_in[1] o_emb f32 (VOCAB+1,50)
//   d_in[2] target (B,) | d_in[3] context (B,10) | d_in[4] neg (B,10)
// Output: scalar f32 = -( sum log_sigmoid(pos) + sum log_sigmoid(-neg) )
//
// Rows are 200 B at 8B alignment; bulk copies use the 16B-aligned 224 B
// window (same sectors, zero extra DRAM traffic); SMEM read offset = off&15.
// (VOCAB+1)-row table keeps the window in-bounds for all wids < VOCAB.

#define DIM2  25
#define CTX   10
#define NNEG  10
#define OSLOT 11      // 1 target + 10 neg per task
#define ROWB  200u
#define SLOTB 224
#define MAX_BLOCKS 8192

__device__ float        g_partials[MAX_BLOCKS];
__device__ unsigned int g_count = 0;   // reset by last block each launch

__device__ __forceinline__ float log_sigmoid(float x) {
    return fminf(x, 0.0f) - __logf(1.0f + __expf(-fabsf(x)));
}

__device__ __forceinline__ void mbar_init(unsigned mbar, unsigned cnt) {
    asm volatile("mbarrier.init.shared.b64 [%0], %1;" :: "r"(mbar), "r"(cnt) : "memory");
}
__device__ __forceinline__ void mbar_expect_tx(unsigned mbar, unsigned bytes) {
    asm volatile("mbarrier.arrive.expect_tx.shared.b64 _, [%0], %1;"
                 :: "r"(mbar), "r"(bytes) : "memory");
}
__device__ __forceinline__ void mbar_wait(unsigned mbar, unsigned parity) {
    asm volatile(
        "{\n\t.reg .pred P;\n"
        "W%=:\n\t"
        "mbarrier.try_wait.parity.shared.b64 P, [%0], %1;\n\t"
        "@!P bra W%=;\n\t}"
        :: "r"(mbar), "r"(parity) : "memory");
}
__device__ __forceinline__ void bulk_cp(unsigned dst, const void* src,
                                        unsigned bytes, unsigned mbar) {
    asm volatile(
        "cp.async.bulk.shared::cluster.global.mbarrier::complete_tx::bytes "
        "[%0], [%1], %2, [%3];"
        :: "r"(dst), "l"(src), "r"(bytes), "r"(mbar) : "memory");
}
__device__ __forceinline__ float2 lds64(unsigned addr) {
    float2 r;
    asm volatile("ld.shared.v2.f32 {%0,%1}, [%2];"
                 : "=f"(r.x), "=f"(r.y) : "r"(addr));
    return r;
}

// 5-shfl pairwise warp reduction: lane 0 gets sum(A), lane 16 gets sum(B).
__device__ __forceinline__ float pair_reduce(float A, float B, int lane) {
    float x = (lane & 16) ? A : B;
    float y = __shfl_xor_sync(0xFFFFFFFFu, x, 16);
    float v = ((lane & 16) ? B : A) + y;
    v += __shfl_xor_sync(0xFFFFFFFFu, v, 8);
    v += __shfl_xor_sync(0xFFFFFFFFu, v, 4);
    v += __shfl_xor_sync(0xFFFFFFFFu, v, 2);
    v += __shfl_xor_sync(0xFFFFFFFFu, v, 1);
    return v;
}

__global__ void __launch_bounds__(256) cbow_dual_kernel(
    const float* __restrict__ i_emb,
    const float* __restrict__ o_emb,
    const int*   __restrict__ target_wids,
    const int*   __restrict__ context_wids,
    const int*   __restrict__ neg_wids,
    float*       __restrict__ out,
    int B)
{
    __shared__ __align__(16) char stage[8][OSLOT * SLOTB];   // 19712 B
    __shared__ __align__(8)  unsigned long long mbar[8];
    __shared__ float  s_partial[8];
    __shared__ int    s_is_last;
    __shared__ double s_d[8];

    const int warp_global = (blockIdx.x * blockDim.x + threadIdx.x) >> 5;
    const int lane        = threadIdx.x & 31;
    const int warp_local  = threadIdx.x >> 5;

    float loss = 0.0f;

    if (warp_global < B) {
        const float2* __restrict__ i2 = (const float2*)i_emb;
        const char*   __restrict__ ob = (const char*)o_emb;
        const int*    __restrict__ cw = context_wids + warp_global * CTX;
        const int*    __restrict__ nw = neg_wids     + warp_global * NNEG;

        const unsigned sb = (unsigned)__cvta_generic_to_shared(stage[warp_local]);
        const unsigned mb = (unsigned)__cvta_generic_to_shared(&mbar[warp_local]);

        // ---- mbarrier setup (fresh each launch; phase 0) ----
        if (lane == 0) {
            mbar_init(mb, 1);
            asm volatile("fence.proxy.async.shared::cta;" ::: "memory");
            mbar_expect_tx(mb, OSLOT * SLOTB);
        }
        __syncwarp();

        // ---- o_emb rows via bulk-async path (lane s owns slot s) ----
        unsigned ooff;                       // this lane's o-row byte offset
        if (lane < OSLOT) {
            int idx = (lane == 0) ? __ldg(&target_wids[warp_global])
                                  : __ldg(&nw[lane - 1]);
            ooff = (unsigned)idx * ROWB;
            bulk_cp(sb + lane * SLOTB, ob + (ooff & ~15u), SLOTB, mb);
        }

        // ---- i_emb ctx rows via LDG path (overlaps with bulk flight) ----
        int cb[CTX];
        #pragma unroll
        for (int c = 0; c < CTX; c++) cb[c] = __ldg(&cw[c]) * DIM2;

        float ax = 0.0f, ay = 0.0f;
        if (lane < DIM2) {
            #pragma unroll
            for (int c = 0; c < CTX; c++) {
                const float2 e = __ldg(&i2[cb[c] + lane]);
                ax += e.x;  ay += e.y;
            }
        }

        // broadcast each slot's in-slot offset (off & 15) to the whole warp
        unsigned inoff[OSLOT];
        #pragma unroll
        for (int s = 0; s < OSLOT; s++)
            inoff[s] = __shfl_sync(0xFFFFFFFFu, ooff & 15u, s);

        // ---- wait for all 11 bulk copies, then score from SMEM ----
        mbar_wait(mb, 0);

        float p[OSLOT];
        #pragma unroll
        for (int k = 0; k < OSLOT; k++) p[k] = 0.0f;

        if (lane < DIM2) {
            const unsigned le = lane * 8;
            #pragma unroll
            for (int s = 0; s < OSLOT; s++) {
                const float2 e = lds64(sb + s * SLOTB + inoff[s] + le);
                p[s] = e.x * ax + e.y * ay;
            }
        }

        const float inv_ctx = 1.0f / CTX;

        // pair 0: (pos, neg0) — mixed signs
        {
            float v = pair_reduce(p[0], p[1], lane);
            if ((lane & 15) == 0) {
                float sc = v * inv_ctx;
                loss += log_sigmoid((lane & 16) ? -sc : sc);
            }
        }
        // pairs (neg1,neg2) (neg3,neg4) (neg5,neg6) (neg7,neg8)
        #pragma unroll
        for (int k = 2; k <= 8; k += 2) {
            float v = pair_reduce(p[k], p[k + 1], lane);
            if ((lane & 15) == 0)
                loss += log_sigmoid(-v * inv_ctx);
        }
        // leftover neg9
        {
            float v = p[10];
            #pragma unroll
            for (int o = 16; o > 0; o >>= 1)
                v += __shfl_xor_sync(0xFFFFFFFFu, v, o);
            if (lane == 0)
                loss += log_sigmoid(-v * inv_ctx);
        }
    }

    // combine lanes 0 and 16
    loss += __shfl_xor_sync(0xFFFFFFFFu, loss, 16);
    if (lane == 0) s_partial[warp_local] = loss;
    __syncthreads();

    // block partial + last-block ticket
    if (threadIdx.x == 0) {
        float blk = 0.0f;
        #pragma unroll
        for (int i = 0; i < 8; i++) blk += s_partial[i];
        g_partials[blockIdx.x] = blk;
        __threadfence();
        unsigned int old = atomicAdd(&g_count, 1u);
        s_is_last = (old == gridDim.x - 1);
    }
    __syncthreads();

    if (s_is_last) {
        const int nb2 = gridDim.x;
        volatile float* vp = g_partials;
        double acc = 0.0;
        for (int i = threadIdx.x; i < nb2; i += 256)
            acc += (double)vp[i];
        #pragma unroll
        for (int o = 16; o > 0; o >>= 1)
            acc += __shfl_xor_sync(0xFFFFFFFFu, acc, o);
        if ((threadIdx.x & 31) == 0) s_d[threadIdx.x >> 5] = acc;
        __syncthreads();
        if (threadIdx.x == 0) {
            double t = 0.0;
            #pragma unroll
            for (int i = 0; i < 8; i++) t += s_d[i];
            out[0] = (float)(-t);
            g_count = 0;
        }
    }
}

extern "C" void kernel_launch(void* const* d_in, const int* in_sizes, int n_in,
                              void* d_out, int out_size)
{
    const float* i_emb        = (const float*)d_in[0];
    const float* o_emb        = (const float*)d_in[1];
    const int*   target_wids  = (const int*)d_in[2];
    const int*   context_wids = (const int*)d_in[3];
    const int*   neg_wids     = (const int*)d_in[4];
    float*       out          = (float*)d_out;

    const int B = in_sizes[2];
    const int rows_per_block = 8;           // 8 warps x 1 task
    int blocks = (B + rows_per_block - 1) / rows_per_block;
    if (blocks > MAX_BLOCKS) blocks = MAX_BLOCKS;   // B=16384 -> 2048

    cbow_dual_kernel<<<blocks, 256>>>(i_emb, o_emb, target_wids,
                                      context_wids, neg_wids, out, B);
}